// round 10
// baseline (speedup 1.0000x reference)
#include <cuda_runtime.h>

#define BB     32
#define DIM    4096
#define NQ     32
#define NKV    8
#define HD     128
#define MAXSEQ 2048
#define NTOT_QKV 6144
#define SK_QKV 12
#define SK_O   18
#define BN     512
#define BK     16
#define NKT    (DIM/BK)       // 256 k-tiles
#define WPAD   516            // floats per k-row of ws (512 + 4, 16B-aligned rows)
#define XPAD   34             // ulls per k-row of xs (32 + 2, 16B-aligned rows)
#define PARTSTRIDE (BB*NTOT_QKV)

// Scratch (device globals — no allocation allowed)
__device__ float g_part[SK_O * PARTSTRIDE];
__device__ float g_q[BB * NQ * HD];
__device__ float g_k[BB * NKV * HD];
__device__ float g_v[BB * NKV * HD];
__device__ float g_att[BB * NQ * HD];

// ---------------------------------------------------------------------------
// f32x2 helpers
// ---------------------------------------------------------------------------
__device__ __forceinline__ void fma2(unsigned long long& d,
                                     unsigned long long a,
                                     unsigned long long b)
{
    asm("fma.rn.f32x2 %0, %1, %2, %3;" : "=l"(d) : "l"(a), "l"(b), "l"(d));
}

__device__ __forceinline__ unsigned long long dup2(float w)
{
    unsigned long long r;
    unsigned int wi = __float_as_uint(w);
    asm("mov.b64 %0, {%1, %1};" : "=l"(r) : "r"(wi));
    return r;
}

// ---------------------------------------------------------------------------
// GEMM (f32x2): part[kc][b][f] = sum_{k in chunk kc} A[b][k] * W[f][k]
// BN=512 features, all 32 batches, BK=16, double-buffered.
// ws k-major (f contiguous): LDS.128 gives 2 (f,f+1) weight pairs directly.
// xs pre-duplicated (x,x) f32x2: no packing movs in the inner loop.
// Warp = 64 features; lane -> fgrp(4)=16f each, bgrp(8)=4b each.
// Thread tile: 8 f-pairs x 4 batches = 32 FFMA2 per k, 6 LDS.128 per k.
// ---------------------------------------------------------------------------
__global__ __launch_bounds__(256) void gemm2_kernel(
    const float* __restrict__ A,  const float* __restrict__ W0,
    const float* __restrict__ W1, const float* __restrict__ W2,
    int ntot, int splitk, int use_att)
{
    __shared__ float ws[2][BK][WPAD];
    __shared__ __align__(16) unsigned long long xs[2][BK][XPAD];

    const float* Ap = use_att ? g_att : A;
    int tid   = threadIdx.x;
    int fbase = blockIdx.x * BN;
    int kc    = blockIdx.y;
    int t0 = (kc * NKT) / splitk;
    int t1 = ((kc + 1) * NKT) / splitk;

    // Select weight matrix (uniform per block; 512 | 1024 so no straddle)
    const float* Wm; int flb;
    if (fbase < 4096)      { Wm = W0; flb = fbase; }
    else if (fbase < 5120) { Wm = W1; flb = fbase - 4096; }
    else                   { Wm = W2; flb = fbase - 5120; }

    int warp = tid >> 5, lane = tid & 31;
    int fgrp = lane & 3, bgrp = lane >> 2;
    int f0 = warp * 64 + fgrp * 16;   // local feature base (floats)
    int b0 = bgrp * 4;                // batch base

    // W staging map: thread loads 8 rows f = sf + i*64, k-quad skq (coalesced 64B runs)
    int sf  = tid >> 2;
    int skq = (tid & 3) * 4;
    // x staging map: batch xb, k-pair xk
    int xb = tid >> 3;
    int xk = (tid & 7) * 2;

    unsigned long long acc[32];
    #pragma unroll
    for (int i = 0; i < 32; i++) acc[i] = 0ULL;

    // Prologue: stage tile t0 -> buffer 0
    {
        int kn = t0 * BK;
        #pragma unroll
        for (int i = 0; i < 8; i++) {
            float4 wv = *(const float4*)&Wm[(size_t)(flb + sf + i * 64) * DIM + kn + skq];
            ws[0][skq + 0][sf + i * 64] = wv.x;
            ws[0][skq + 1][sf + i * 64] = wv.y;
            ws[0][skq + 2][sf + i * 64] = wv.z;
            ws[0][skq + 3][sf + i * 64] = wv.w;
        }
        float2 xv = *(const float2*)&Ap[(size_t)xb * DIM + kn + xk];
        xs[0][xk + 0][xb] = dup2(xv.x);
        xs[0][xk + 1][xb] = dup2(xv.y);
    }
    __syncthreads();

    for (int t = t0; t < t1; t++) {
        int cur = (t - t0) & 1;
        bool more = (t + 1 < t1);
        float4 wst[8];
        float2 xst;
        if (more) {
            int kn = (t + 1) * BK;
            #pragma unroll
            for (int i = 0; i < 8; i++)
                wst[i] = *(const float4*)&Wm[(size_t)(flb + sf + i * 64) * DIM + kn + skq];
            xst = *(const float2*)&Ap[(size_t)xb * DIM + kn + xk];
        }

        #pragma unroll
        for (int k = 0; k < BK; k++) {
            const ulonglong2* wp = (const ulonglong2*)&ws[cur][k][f0];
            ulonglong2 w01 = wp[0], w23 = wp[1], w45 = wp[2], w67 = wp[3];
            const ulonglong2* xp = (const ulonglong2*)&xs[cur][k][b0];
            ulonglong2 xA = xp[0], xB = xp[1];

            fma2(acc[ 0], w01.x, xA.x); fma2(acc[ 1], w01.x, xA.y);
            fma2(acc[ 2], w01.x, xB.x); fma2(acc[ 3], w01.x, xB.y);
            fma2(acc[ 4], w01.y, xA.x); fma2(acc[ 5], w01.y, xA.y);
            fma2(acc[ 6], w01.y, xB.x); fma2(acc[ 7], w01.y, xB.y);
            fma2(acc[ 8], w23.x, xA.x); fma2(acc[ 9], w23.x, xA.y);
            fma2(acc[10], w23.x, xB.x); fma2(acc[11], w23.x, xB.y);
            fma2(acc[12], w23.y, xA.x); fma2(acc[13], w23.y, xA.y);
            fma2(acc[14], w23.y, xB.x); fma2(acc[15], w23.y, xB.y);
            fma2(acc[16], w45.x, xA.x); fma2(acc[17], w45.x, xA.y);
            fma2(acc[18], w45.x, xB.x); fma2(acc[19], w45.x, xB.y);
            fma2(acc[20], w45.y, xA.x); fma2(acc[21], w45.y, xA.y);
            fma2(acc[22], w45.y, xB.x); fma2(acc[23], w45.y, xB.y);
            fma2(acc[24], w67.x, xA.x); fma2(acc[25], w67.x, xA.y);
            fma2(acc[26], w67.x, xB.x); fma2(acc[27], w67.x, xB.y);
            fma2(acc[28], w67.y, xA.x); fma2(acc[29], w67.y, xA.y);
            fma2(acc[30], w67.y, xB.x); fma2(acc[31], w67.y, xB.y);
        }

        if (more) {
            int nb = 1 - cur;
            #pragma unroll
            for (int i = 0; i < 8; i++) {
                ws[nb][skq + 0][sf + i * 64] = wst[i].x;
                ws[nb][skq + 1][sf + i * 64] = wst[i].y;
                ws[nb][skq + 2][sf + i * 64] = wst[i].z;
                ws[nb][skq + 3][sf + i * 64] = wst[i].w;
            }
            xs[nb][xk + 0][xb] = dup2(xst.x);
            xs[nb][xk + 1][xb] = dup2(xst.y);
        }
        __syncthreads();
    }

    // Epilogue: acc[p*4+bj] holds features (fg+2p, fg+2p+1) of batch b0+bj -> STG.64
    float* po = g_part + (size_t)kc * PARTSTRIDE;
    int fg = fbase + f0;
    #pragma unroll
    for (int p = 0; p < 8; p++) {
        #pragma unroll
        for (int bj = 0; bj < 4; bj++) {
            *(unsigned long long*)&po[(size_t)(b0 + bj) * ntot + fg + 2 * p] =
                acc[p * 4 + bj];
        }
    }
}

// ---------------------------------------------------------------------------
// Combine QKV split-K partials (SK_QKV), apply RoPE, scatter to g_q/g_k/g_v.
// ---------------------------------------------------------------------------
__global__ void combine_rope_kernel(const float* __restrict__ cosv,
                                    const float* __restrict__ sinv)
{
    int idx = blockIdx.x * 256 + threadIdx.x;
    if (idx >= BB * 3072) return;
    int b  = idx / 3072;
    int f0 = (idx % 3072) * 2;

    size_t o = (size_t)b * NTOT_QKV + f0;
    float v0 = 0.f, v1 = 0.f;
    #pragma unroll
    for (int c = 0; c < SK_QKV; c++) {
        float2 t = *(const float2*)&g_part[o + (size_t)c * PARTSTRIDE];
        v0 += t.x; v1 += t.y;
    }

    if (f0 < 5120) {  // q or k: RoPE (S=1, position = start_pos)
        int d2 = (f0 & (HD - 1)) >> 1;
        float c = cosv[d2], s = sinv[d2];
        float r0 = v0 * c - v1 * s;
        float r1 = v0 * s + v1 * c;
        v0 = r0; v1 = r1;
    }
    if (f0 < 4096) {
        g_q[(size_t)b * 4096 + f0]     = v0;
        g_q[(size_t)b * 4096 + f0 + 1] = v1;
    } else if (f0 < 5120) {
        g_k[(size_t)b * 1024 + (f0 - 4096)]     = v0;
        g_k[(size_t)b * 1024 + (f0 - 4096) + 1] = v1;
    } else {
        g_v[(size_t)b * 1024 + (f0 - 5120)]     = v0;
        g_v[(size_t)b * 1024 + (f0 - 5120) + 1] = v1;
    }
}

// ---------------------------------------------------------------------------
// Attention. No max-tracking (scores are O(5): exp() safe, identical softmax).
// Folded 4-way warp reduction; 4-step load batching for MLP=8 per warp.
// ---------------------------------------------------------------------------
__device__ __forceinline__ void step_compute(
    float4 kv, float4 vv, const float4 q[4], float l[4], float4 o[4], int lane)
{
    float s0 = q[0].x*kv.x + q[0].y*kv.y + q[0].z*kv.z + q[0].w*kv.w;
    float s1 = q[1].x*kv.x + q[1].y*kv.y + q[1].z*kv.z + q[1].w*kv.w;
    float s2 = q[2].x*kv.x + q[2].y*kv.y + q[2].z*kv.z + q[2].w*kv.w;
    float s3 = q[3].x*kv.x + q[3].y*kv.y + q[3].z*kv.z + q[3].w*kv.w;

    // Fold 4 sums -> lane groups: [0-7]=s0, [8-15]=s1, [16-23]=s2, [24-31]=s3
    bool hi16 = (lane & 16) != 0;
    float a = (hi16 ? s2 : s0) + __shfl_xor_sync(0xffffffffu, hi16 ? s0 : s2, 16);
    float bb = (hi16 ? s3 : s1) + __shfl_xor_sync(0xffffffffu, hi16 ? s1 : s3, 16);
    bool hi8 = (lane & 8) != 0;
    float c = (hi8 ? bb : a) + __shfl_xor_sync(0xffffffffu, hi8 ? a : bb, 8);
    c += __shfl_xor_sync(0xffffffffu, c, 4);
    c += __shfl_xor_sync(0xffffffffu, c, 2);
    c += __shfl_xor_sync(0xffffffffu, c, 1);

    float pe = __expf(c);
    float p0 = __shfl_sync(0xffffffffu, pe, 0);
    float p1 = __shfl_sync(0xffffffffu, pe, 8);
    float p2 = __shfl_sync(0xffffffffu, pe, 16);
    float p3 = __shfl_sync(0xffffffffu, pe, 24);

    l[0] += p0; l[1] += p1; l[2] += p2; l[3] += p3;
    o[0].x += p0*vv.x; o[0].y += p0*vv.y; o[0].z += p0*vv.z; o[0].w += p0*vv.w;
    o[1].x += p1*vv.x; o[1].y += p1*vv.y; o[1].z += p1*vv.z; o[1].w += p1*vv.w;
    o[2].x += p2*vv.x; o[2].y += p2*vv.y; o[2].z += p2*vv.z; o[2].w += p2*vv.w;
    o[3].x += p3*vv.x; o[3].y += p3*vv.y; o[3].z += p3*vv.z; o[3].w += p3*vv.w;
}

__global__ __launch_bounds__(256, 2) void attn_kernel(
    const float* __restrict__ ck, const float* __restrict__ cv,
    const int* __restrict__ spp)
{
    int bgid = blockIdx.x;
    int b = bgid >> 3, g = bgid & 7;
    int tid = threadIdx.x;
    int warp = tid >> 5, lane = tid & 31;

    int sp = *spp;
    int T  = sp + 1; if (T > MAXSEQ) T = MAXSEQ;

    const float scale = 0.08838834764831845f;  // 1/sqrt(128)

    float4 q[4];
    #pragma unroll
    for (int r = 0; r < 4; r++) {
        float4 t = *(const float4*)&g_q[((size_t)b * NQ + g * 4 + r) * HD + lane * 4];
        q[r].x = t.x * scale; q[r].y = t.y * scale;
        q[r].z = t.z * scale; q[r].w = t.w * scale;
    }

    float l[4] = {0.f, 0.f, 0.f, 0.f};
    float4 o[4];
    #pragma unroll
    for (int r = 0; r < 4; r++) o[r] = make_float4(0.f, 0.f, 0.f, 0.f);

    const float* kbase = ck + (size_t)b * MAXSEQ * NKV * HD + (size_t)g * HD + lane * 4;
    const float* vbase = cv + (size_t)b * MAXSEQ * NKV * HD + (size_t)g * HD + lane * 4;
    const float* knew  = &g_k[((size_t)b * NKV + g) * HD + lane * 4];
    const float* vnew  = &g_v[((size_t)b * NKV + g) * HD + lane * 4];

    int t = warp;
    for (; t + 24 < T; t += 32) {
        float4 kv[4], vv[4];
        #pragma unroll
        for (int u = 0; u < 4; u++) {
            int tu = t + 8 * u;
            const float* kp = (tu == sp) ? knew : kbase + (size_t)tu * (NKV * HD);
            kv[u] = *(const float4*)kp;
        }
        #pragma unroll
        for (int u = 0; u < 4; u++) {
            int tu = t + 8 * u;
            const float* vp = (tu == sp) ? vnew : vbase + (size_t)tu * (NKV * HD);
            vv[u] = *(const float4*)vp;
        }
        #pragma unroll
        for (int u = 0; u < 4; u++)
            step_compute(kv[u], vv[u], q, l, o, lane);
    }
    for (; t < T; t += 8) {
        const float* kp = (t == sp) ? knew : kbase + (size_t)t * (NKV * HD);
        const float* vp = (t == sp) ? vnew : vbase + (size_t)t * (NKV * HD);
        float4 kv = *(const float4*)kp;
        float4 vv = *(const float4*)vp;
        step_compute(kv, vv, q, l, o, lane);
    }

    __shared__ float l_s[8][4];
    __shared__ float o_s[8][4][HD];
    #pragma unroll
    for (int r = 0; r < 4; r++) {
        if (lane == 0) l_s[warp][r] = l[r];
        *(float4*)&o_s[warp][r][lane * 4] = o[r];
    }
    __syncthreads();

    for (int idx = tid; idx < 4 * HD; idx += 256) {
        int r = idx >> 7, d = idx & (HD - 1);
        float L = 0.f, O = 0.f;
        #pragma unroll
        for (int w = 0; w < 8; w++) {
            L += l_s[w][r];
            O += o_s[w][r][d];
        }
        g_att[((size_t)b * NQ + g * 4 + r) * HD + d] = O / L;
    }
}

// ---------------------------------------------------------------------------
// Sum SK_O o-proj partials into d_out (float4 per thread).
// ---------------------------------------------------------------------------
__global__ void combine_out_kernel(float* __restrict__ out)
{
    int idx = (blockIdx.x * 256 + threadIdx.x) * 4;   // 32*4096 floats total
    float4 s = make_float4(0.f, 0.f, 0.f, 0.f);
    #pragma unroll
    for (int c = 0; c < SK_O; c++) {
        float4 t = *(const float4*)&g_part[(size_t)c * PARTSTRIDE + idx];
        s.x += t.x; s.y += t.y; s.z += t.z; s.w += t.w;
    }
    *(float4*)&out[idx] = s;
}

// ---------------------------------------------------------------------------
extern "C" void kernel_launch(void* const* d_in, const int* in_sizes, int n_in,
                              void* d_out, int out_size)
{
    const float* x  = (const float*)d_in[0];
    const float* wq = (const float*)d_in[1];
    const float* wk = (const float*)d_in[2];
    const float* wv = (const float*)d_in[3];
    const float* wo = (const float*)d_in[4];
    const float* fc = (const float*)d_in[5];
    const float* fs = (const float*)d_in[6];
    const float* ck = (const float*)d_in[7];
    const float* cv = (const float*)d_in[8];
    const int*   sp = (const int*)d_in[9];
    float* out = (float*)d_out;

    // QKV fused: 12 f-blocks x 12 k-chunks = 144 blocks (one per SM)
    gemm2_kernel<<<dim3(12, SK_QKV), 256>>>(x, wq, wk, wv, NTOT_QKV, SK_QKV, 0);
    // Combine + RoPE + scatter
    combine_rope_kernel<<<384, 256>>>(fc, fs);
    // Attention over KV cache (new token substituted from g_k/g_v)
    attn_kernel<<<BB * NKV, 256>>>(ck, cv, sp);
    // Output projection: 8 f-blocks x 18 k-chunks = 144 blocks
    gemm2_kernel<<<dim3(8, SK_O), 256>>>(nullptr, wo, wo, wo, 4096, SK_O, 1);
    // Final combine into d_out
    combine_out_kernel<<<128, 256>>>(out);
}